// round 2
// baseline (speedup 1.0000x reference)
#include <cuda_runtime.h>
#include <cuda_bf16.h>
#include <cstdint>

#define B_ 64
#define S_ 2048
#define D_ 512

// ---------- scratch (no allocations allowed) ----------
__device__ float g_wq[B_ * D_];       // source @ Wq^T + bq
__device__ float g_scores[B_ * S_];   // raw scores (pre-mask)
__device__ float g_stats[2 * B_];     // {max, sumexp} per batch

// ---------- helpers ----------
__device__ __forceinline__ float to_tf32(float x) {
    asm("cvt.rna.tf32.f32 %0, %0;" : "+f"(x));
    return x;
}

__device__ __forceinline__ float fast_tanh(float x) {
    float xc = fminf(fmaxf(x, -15.f), 15.f);
    float e = __expf(2.f * xc);
    return __fdividef(e - 1.f, e + 1.f);
}

// memory_lengths may be int64 (as written in reference) or int32 (JAX x64
// disabled silently downcasts). Little-endian sniff: word[1] is the high word
// of lens[0] (== 0) for int64; it's lens[1] in [1,2048] (never 0) for int32.
__device__ __forceinline__ int load_len(const void* lens, int b) {
    const int* p32 = (const int*)lens;
    if (p32[1] == 0) return (int)((const long long*)lens)[b];
    return p32[b];
}

// ============================================================
// Kernel 1: wq[b,e] = bq[e] + sum_d source[b,d] * Wq[e,d]
// grid (4, B), block 128
// ============================================================
__global__ void wq_kernel(const float* __restrict__ src,
                          const float* __restrict__ Wq,
                          const float* __restrict__ bq) {
    int b = blockIdx.y;
    int e = blockIdx.x * 128 + threadIdx.x;
    __shared__ __align__(16) float s_src[D_];
    for (int i = threadIdx.x; i < D_; i += 128) s_src[i] = src[b * D_ + i];
    __syncthreads();

    const float4* w4 = (const float4*)(Wq + (size_t)e * D_);
    const float4* s4 = (const float4*)s_src;
    float acc = 0.f;
#pragma unroll 8
    for (int i = 0; i < D_ / 4; ++i) {
        float4 wv = w4[i];
        float4 xv = s4[i];
        acc += wv.x * xv.x + wv.y * xv.y + wv.z * xv.z + wv.w * xv.w;
    }
    g_wq[b * D_ + e] = acc + bq[e];
}

// ============================================================
// Kernel 2: fused  scores[b,s] = sum_e tanh(wq[b,e] + (mb @ Wc^T)[s,e]) * v[e]
// tf32 mma.sync m16n8k8. One CTA = one batch x 64 S-rows.
// grid (S/64, B), block 256 (8 warps: 4 warp-rows x 2 warp-cols over 64x128)
// ============================================================
#define TILE_M 64
#define TILE_N 128
#define TILE_K 64
#define AS_STRIDE 516   // (516 % 32) = 4 -> conflict-free A-frag LDS
#define BS_STRIDE 136   // (136 % 32) = 8 -> conflict-free B-frag LDS

#define SMEM_WORDS (TILE_M * AS_STRIDE + TILE_K * BS_STRIDE + D_ + D_ + 128)
#define SMEM_BYTES (SMEM_WORDS * 4)

__global__ void scores_kernel(const float* __restrict__ mb,
                              const float* __restrict__ Wc,
                              const float* __restrict__ vvec) {
    extern __shared__ __align__(16) float sm[];
    float* As    = sm;                         // [64][516]
    float* Bs    = As + TILE_M * AS_STRIDE;    // [64 k][136 e]
    float* swq   = Bs + TILE_K * BS_STRIDE;    // [512]
    float* sv    = swq + D_;                   // [512]
    float* spart = sv + D_;                    // [8 warps][16 rows]

    const int b   = blockIdx.y;
    const int s0  = blockIdx.x * TILE_M;
    const int tid = threadIdx.x;
    const int warp = tid >> 5, lane = tid & 31;
    const int g = lane >> 2, t = lane & 3;      // groupID / threadInGroup
    const int wr = warp >> 1, wc = warp & 1;
    const int m_off = wr * 16;

    for (int i = tid; i < D_; i += 256) {
        swq[i] = g_wq[b * D_ + i];
        sv[i]  = vvec[i];
    }

    // A tile: 64 x 512 fp32 -> tf32-rounded into smem
    {
        const float4* src4 = (const float4*)(mb + (size_t)b * S_ * D_ + (size_t)s0 * D_);
        for (int i = tid; i < TILE_M * (D_ / 4); i += 256) {
            int r  = i >> 7;
            int c4 = i & 127;
            float4 val = src4[r * (D_ / 4) + c4];
            float* dst = As + r * AS_STRIDE + c4 * 4;
            dst[0] = to_tf32(val.x);
            dst[1] = to_tf32(val.y);
            dst[2] = to_tf32(val.z);
            dst[3] = to_tf32(val.w);
        }
    }

    float sum0 = 0.f, sum1 = 0.f;   // rows m_off+g, m_off+g+8

    for (int nb = 0; nb < D_; nb += TILE_N) {
        float acc[8][4];
#pragma unroll
        for (int j = 0; j < 8; ++j)
#pragma unroll
            for (int q = 0; q < 4; ++q) acc[j][q] = 0.f;

        for (int kb = 0; kb < D_; kb += TILE_K) {
            __syncthreads();
            // load Wc[nb+r][kb+c] -> Bs[c][r]  (transposed, tf32-rounded)
            for (int i = tid; i < TILE_N * (TILE_K / 4); i += 256) {
                int r  = i >> 4;
                int c4 = i & 15;
                float4 val = *(const float4*)(Wc + (size_t)(nb + r) * D_ + kb + c4 * 4);
                int c = c4 * 4;
                Bs[(c + 0) * BS_STRIDE + r] = to_tf32(val.x);
                Bs[(c + 1) * BS_STRIDE + r] = to_tf32(val.y);
                Bs[(c + 2) * BS_STRIDE + r] = to_tf32(val.z);
                Bs[(c + 3) * BS_STRIDE + r] = to_tf32(val.w);
            }
            __syncthreads();

#pragma unroll 2
            for (int kk = 0; kk < TILE_K; kk += 8) {
                const float* arow0 = As + (m_off + g) * AS_STRIDE + kb + kk + t;
                const float* arow1 = As + (m_off + g + 8) * AS_STRIDE + kb + kk + t;
                uint32_t a0 = __float_as_uint(arow0[0]);
                uint32_t a1 = __float_as_uint(arow1[0]);
                uint32_t a2 = __float_as_uint(arow0[4]);
                uint32_t a3 = __float_as_uint(arow1[4]);
#pragma unroll
                for (int j = 0; j < 8; ++j) {
                    int ecol = wc * 64 + j * 8 + g;
                    uint32_t b0 = __float_as_uint(Bs[(kk + t) * BS_STRIDE + ecol]);
                    uint32_t b1 = __float_as_uint(Bs[(kk + t + 4) * BS_STRIDE + ecol]);
                    asm volatile(
                        "mma.sync.aligned.m16n8k8.row.col.f32.tf32.tf32.f32 "
                        "{%0,%1,%2,%3}, {%4,%5,%6,%7}, {%8,%9}, {%0,%1,%2,%3};"
                        : "+f"(acc[j][0]), "+f"(acc[j][1]),
                          "+f"(acc[j][2]), "+f"(acc[j][3])
                        : "r"(a0), "r"(a1), "r"(a2), "r"(a3), "r"(b0), "r"(b1));
                }
            }
        }

#pragma unroll
        for (int j = 0; j < 8; ++j) {
            int e = nb + wc * 64 + j * 8 + 2 * t;
            float wq0 = swq[e],     wq1 = swq[e + 1];
            float v0  = sv[e],      v1  = sv[e + 1];
            sum0 += fast_tanh(wq0 + acc[j][0]) * v0 + fast_tanh(wq1 + acc[j][1]) * v1;
            sum1 += fast_tanh(wq0 + acc[j][2]) * v0 + fast_tanh(wq1 + acc[j][3]) * v1;
        }
    }

    sum0 += __shfl_xor_sync(0xFFFFFFFFu, sum0, 1);
    sum0 += __shfl_xor_sync(0xFFFFFFFFu, sum0, 2);
    sum1 += __shfl_xor_sync(0xFFFFFFFFu, sum1, 1);
    sum1 += __shfl_xor_sync(0xFFFFFFFFu, sum1, 2);
    if (t == 0) {
        spart[warp * 16 + g]     = sum0;
        spart[warp * 16 + g + 8] = sum1;
    }
    __syncthreads();

    if (tid < TILE_M) {
        int mm  = tid & 15;
        int wr2 = tid >> 4;
        float sc = spart[(wr2 * 2 + 0) * 16 + mm] + spart[(wr2 * 2 + 1) * 16 + mm];
        g_scores[b * S_ + s0 + tid] = sc;
    }
}

// ============================================================
// Kernel 3: masked softmax stats per batch (max, sumexp)
// grid B, block 256
// ============================================================
__global__ void stats_kernel(const void* __restrict__ lens) {
    __shared__ float red[256];
    int b = blockIdx.x, tid = threadIdx.x;
    int len = load_len(lens, b);

    float m = -3.4e38f;
    for (int s = tid; s < S_; s += 256)
        if (s < len) m = fmaxf(m, g_scores[b * S_ + s]);
    red[tid] = m;
    __syncthreads();
    for (int o = 128; o > 0; o >>= 1) {
        if (tid < o) red[tid] = fmaxf(red[tid], red[tid + o]);
        __syncthreads();
    }
    m = red[0];
    __syncthreads();

    float sum = 0.f;
    for (int s = tid; s < S_; s += 256)
        if (s < len) sum += __expf(g_scores[b * S_ + s] - m);
    red[tid] = sum;
    __syncthreads();
    for (int o = 128; o > 0; o >>= 1) {
        if (tid < o) red[tid] += red[tid + o];
        __syncthreads();
    }
    if (tid == 0) {
        g_stats[2 * b]     = m;
        g_stats[2 * b + 1] = red[0];
    }
}

// ============================================================
// Kernel 4: align + context. grid (4 d-chunks, B), block 128
// out[0 : B*D] = c,  out[B*D : B*D + B*S] = align
// ============================================================
__global__ void context_kernel(const float* __restrict__ mb,
                               const void* __restrict__ lens,
                               float* __restrict__ out) {
    __shared__ float w[S_];
    int b = blockIdx.y, ch = blockIdx.x, tid = threadIdx.x;
    int len = load_len(lens, b);
    float m = g_stats[2 * b];
    float inv = __fdividef(1.f, g_stats[2 * b + 1]);

    for (int s = tid; s < S_; s += 128)
        w[s] = (s < len) ? __expf(g_scores[b * S_ + s] - m) * inv : 0.f;
    __syncthreads();

    if (ch == 0) {
        float* align_out = out + B_ * D_;
        for (int s = tid; s < S_; s += 128) align_out[b * S_ + s] = w[s];
    }

    int d = ch * 128 + tid;
    const float* p = mb + (size_t)b * S_ * D_ + d;
    float acc = 0.f;
#pragma unroll 4
    for (int s = 0; s < S_; s += 4) {
        float x0 = p[(size_t)(s + 0) * D_];
        float x1 = p[(size_t)(s + 1) * D_];
        float x2 = p[(size_t)(s + 2) * D_];
        float x3 = p[(size_t)(s + 3) * D_];
        acc += w[s] * x0 + w[s + 1] * x1 + w[s + 2] * x2 + w[s + 3] * x3;
    }
    out[b * D_ + d] = acc;
}

// ============================================================
extern "C" void kernel_launch(void* const* d_in, const int* in_sizes, int n_in,
                              void* d_out, int out_size) {
    const float* source = (const float*)d_in[0];
    const float* mb     = (const float*)d_in[1];
    const void*  lens   = (const void*)d_in[2];
    const float* Wq     = (const float*)d_in[3];
    const float* bq     = (const float*)d_in[4];
    const float* Wc     = (const float*)d_in[5];
    const float* v      = (const float*)d_in[6];
    float*       out    = (float*)d_out;

    cudaFuncSetAttribute(scores_kernel,
                         cudaFuncAttributeMaxDynamicSharedMemorySize, SMEM_BYTES);

    wq_kernel<<<dim3(4, B_), 128>>>(source, Wq, bq);
    scores_kernel<<<dim3(S_ / TILE_M, B_), 256, SMEM_BYTES>>>(mb, Wc, v);
    stats_kernel<<<B_, 256>>>(lens);
    context_kernel<<<dim3(4, B_), 128>>>(mb, lens, out);
}

// round 4
// speedup vs baseline: 3.4934x; 3.4934x over previous
#include <cuda_runtime.h>
#include <cuda_bf16.h>
#include <cstdint>

#define B_ 64
#define S_ 2048
#define D_ 512

#define TM 64            // M rows per CTA
#define TK 32            // K per stage tile
#define NKT (D_ / TK)    // 16 k-tiles

// ---------------- scratch globals ----------------
__device__ float g_wq[B_ * D_];
__device__ float g_scores[B_ * S_];
__device__ float g_stats[2 * B_];
__device__ float g_ctx[4][B_ * D_];
// Wc pre-rounded (tf32 RNA), k-major, bank-swizzled: [ktile][k][e ^ ((k&3)<<3)]
__device__ __align__(16) float g_wcT[NKT][TK][D_];

// ---------------- helpers ----------------
__device__ __forceinline__ float to_tf32(float x) {
    asm("cvt.rna.tf32.f32 %0, %0;" : "+f"(x));
    return x;
}
__device__ __forceinline__ float fast_tanh(float x) {
    float xc = fminf(fmaxf(x, -15.f), 15.f);
    float e = __expf(2.f * xc);
    return __fdividef(e - 1.f, e + 1.f);
}
// memory_lengths dtype sniff (int64 vs int32): word[1]==0 iff int64 (LE)
__device__ __forceinline__ int load_len(const void* lens, int b) {
    const int* p32 = (const int*)lens;
    if (p32[1] == 0) return (int)((const long long*)lens)[b];
    return p32[b];
}
__device__ __forceinline__ uint32_t smem_u32(const void* p) {
    uint32_t a;
    asm("{ .reg .u64 t; cvta.to.shared.u64 t, %1; cvt.u32.u64 %0, t; }" : "=r"(a) : "l"(p));
    return a;
}
__device__ __forceinline__ void cp_async16(uint32_t dst, const void* src) {
    asm volatile("cp.async.cg.shared.global [%0], [%1], 16;" :: "r"(dst), "l"(src));
}
__device__ __forceinline__ void mma_tf32(float* c, const uint32_t* a,
                                         uint32_t b0, uint32_t b1) {
    asm volatile(
        "mma.sync.aligned.m16n8k8.row.col.f32.tf32.tf32.f32 "
        "{%0,%1,%2,%3}, {%4,%5,%6,%7}, {%8,%9}, {%0,%1,%2,%3};"
        : "+f"(c[0]), "+f"(c[1]), "+f"(c[2]), "+f"(c[3])
        : "r"(a[0]), "r"(a[1]), "r"(a[2]), "r"(a[3]), "r"(b0), "r"(b1));
}

// ============================================================
// Kernel 0: prep Wc -> g_wcT (tf32 RNA, k-major, swizzled)
// grid 512 (one CTA per e-row), block 512 (one thread per k)
// ============================================================
__global__ void prep_wc_kernel(const float* __restrict__ Wc) {
    int e = blockIdx.x, k = threadIdx.x;
    float v = to_tf32(Wc[(size_t)e * D_ + k]);
    g_wcT[k >> 5][k & 31][e ^ ((k & 3) << 3)] = v;
}

// ============================================================
// Kernel 1: wq = source @ Wq^T + bq.  grid (4, B), block 128
// ============================================================
__global__ void wq_kernel(const float* __restrict__ src,
                          const float* __restrict__ Wq,
                          const float* __restrict__ bq) {
    int b = blockIdx.y;
    int e = blockIdx.x * 128 + threadIdx.x;
    __shared__ __align__(16) float s_src[D_];
    for (int i = threadIdx.x; i < D_; i += 128) s_src[i] = src[b * D_ + i];
    __syncthreads();
    const float4* w4 = (const float4*)(Wq + (size_t)e * D_);
    const float4* s4 = (const float4*)s_src;
    float acc = 0.f;
#pragma unroll 8
    for (int i = 0; i < D_ / 4; ++i) {
        float4 wv = w4[i], xv = s4[i];
        acc += wv.x * xv.x + wv.y * xv.y + wv.z * xv.z + wv.w * xv.w;
    }
    g_wq[b * D_ + e] = acc + bq[e];
}

// ============================================================
// Kernel 2: fused scores, tf32 mma.sync, cp.async double-buffered.
// grid (S/64, B), block 512 (16 warps = 2 wr x 8 wc).
// Warp tile: m32 x n64. Full N=512 in register accumulators.
// ============================================================
#define A_STRIDE 36                 // banks 4g+t -> conflict-free
#define ASZ (TM * A_STRIDE)         // floats per A buffer
#define BSZ (TK * D_)               // floats per B buffer
// smem float layout: As[2] | Bs[2] | swq | sv | spart
#define OF_AS   0
#define OF_BS   (2 * ASZ)
#define OF_WQ   (OF_BS + 2 * BSZ)
#define OF_V    (OF_WQ + D_)
#define OF_PART (OF_V + D_)
#define SMEM_FLOATS (OF_PART + TM * 8)
#define SMEM_BYTES  (SMEM_FLOATS * 4)

__global__ void __launch_bounds__(512, 1)
scores_kernel(const float* __restrict__ mb, const float* __restrict__ vvec) {
    extern __shared__ __align__(16) float sm[];
    float* As    = sm + OF_AS;
    float* Bs    = sm + OF_BS;
    float* swq   = sm + OF_WQ;
    float* sv    = sm + OF_V;
    float* spart = sm + OF_PART;

    const int b   = blockIdx.y;
    const int s0  = blockIdx.x * TM;
    const int tid = threadIdx.x;
    const int wid = tid >> 5, lane = tid & 31;
    const int g = lane >> 2, t = lane & 3;
    const int wr = wid >> 3, wc = wid & 7;
    const int m0 = wr * 32, n0 = wc * 64;

    for (int i = tid; i < D_; i += 512) {
        swq[i] = g_wq[b * D_ + i];
        sv[i]  = vvec[i];
    }

    // staging indices
    const int am  = tid >> 3;          // A row 0..63
    const int ak4 = (tid & 7) * 4;     // A k-offset 0..28
    const float* a_gbase = mb + (size_t)b * S_ * D_ + (size_t)(s0 + am) * D_ + ak4;
    const uint32_t sbase = smem_u32(sm);

    float acc[2][8][4];
#pragma unroll
    for (int mt = 0; mt < 2; ++mt)
#pragma unroll
        for (int j = 0; j < 8; ++j)
#pragma unroll
            for (int q = 0; q < 4; ++q) acc[mt][j][q] = 0.f;

    // ---- prologue: stage tile 0 ----
    {
        const float* bsrc = &g_wcT[0][0][0];
        uint32_t bdst = sbase + (OF_BS) * 4;
#pragma unroll
        for (int c = 0; c < 8; ++c)
            cp_async16(bdst + (tid + c * 512) * 16, bsrc + (tid + c * 512) * 4);
        asm volatile("cp.async.commit_group;" ::: "memory");
        float4 av = *(const float4*)a_gbase;
        float* ad = As + am * A_STRIDE + ak4;
        ad[0] = to_tf32(av.x); ad[1] = to_tf32(av.y);
        ad[2] = to_tf32(av.z); ad[3] = to_tf32(av.w);
    }

#pragma unroll 1
    for (int kb = 0; kb < NKT; ++kb) {
        const int cur = kb & 1;
        float4 av;
        if (kb < NKT - 1) {
            av = *(const float4*)(a_gbase + (kb + 1) * TK);
            const float* bsrc = &g_wcT[kb + 1][0][0];
            uint32_t bdst = sbase + (OF_BS + (cur ^ 1) * BSZ) * 4;
#pragma unroll
            for (int c = 0; c < 8; ++c)
                cp_async16(bdst + (tid + c * 512) * 16, bsrc + (tid + c * 512) * 4);
            asm volatile("cp.async.commit_group;" ::: "memory");
            asm volatile("cp.async.wait_group 1;" ::: "memory");
        } else {
            asm volatile("cp.async.wait_group 0;" ::: "memory");
        }
        __syncthreads();   // As[cur], Bs[cur] ready; prev compute finished

        const float* Ac = As + cur * ASZ;
        const float* Bc = Bs + cur * BSZ;
#pragma unroll
        for (int kk = 0; kk < 4; ++kk) {
            const int k8 = kk * 8;
            uint32_t a[2][4];
#pragma unroll
            for (int mt = 0; mt < 2; ++mt) {
                const float* ap = Ac + (m0 + mt * 16 + g) * A_STRIDE + k8 + t;
                a[mt][0] = __float_as_uint(ap[0]);
                a[mt][1] = __float_as_uint(ap[8 * A_STRIDE]);
                a[mt][2] = __float_as_uint(ap[4]);
                a[mt][3] = __float_as_uint(ap[8 * A_STRIDE + 4]);
            }
#pragma unroll
            for (int j = 0; j < 8; ++j) {
                const int col = (n0 + j * 8 + g) ^ (t << 3);
                uint32_t b0 = __float_as_uint(Bc[(k8 + t) * D_ + col]);
                uint32_t b1 = __float_as_uint(Bc[(k8 + t + 4) * D_ + col]);
                mma_tf32(acc[0][j], a[0], b0, b1);
                mma_tf32(acc[1][j], a[1], b0, b1);
            }
        }

        if (kb < NKT - 1) {   // store prefetched A into next buffer
            float* ad = As + (cur ^ 1) * ASZ + am * A_STRIDE + ak4;
            ad[0] = to_tf32(av.x); ad[1] = to_tf32(av.y);
            ad[2] = to_tf32(av.z); ad[3] = to_tf32(av.w);
        }
        __syncthreads();   // protect Bs[cur] before next iter's cp.async overwrite
    }

    // ---- epilogue: tanh + v dot, reduce ----
    float p[4] = {0.f, 0.f, 0.f, 0.f};
#pragma unroll
    for (int mt = 0; mt < 2; ++mt)
#pragma unroll
        for (int j = 0; j < 8; ++j) {
            const int c = n0 + j * 8 + 2 * t;
            const float v0 = sv[c], v1 = sv[c + 1];
            const float w0 = swq[c], w1 = swq[c + 1];
            p[mt * 2 + 0] += fast_tanh(w0 + acc[mt][j][0]) * v0 +
                             fast_tanh(w1 + acc[mt][j][1]) * v1;
            p[mt * 2 + 1] += fast_tanh(w0 + acc[mt][j][2]) * v0 +
                             fast_tanh(w1 + acc[mt][j][3]) * v1;
        }
#pragma unroll
    for (int q = 0; q < 4; ++q) {
        p[q] += __shfl_xor_sync(0xFFFFFFFFu, p[q], 1);
        p[q] += __shfl_xor_sync(0xFFFFFFFFu, p[q], 2);
    }
    if (t == 0) {
#pragma unroll
        for (int mt = 0; mt < 2; ++mt) {
            spart[(m0 + mt * 16 + g) * 8 + wc]     = p[mt * 2 + 0];
            spart[(m0 + mt * 16 + g + 8) * 8 + wc] = p[mt * 2 + 1];
        }
    }
    __syncthreads();
    if (tid < TM) {
        float s = 0.f;
#pragma unroll
        for (int w = 0; w < 8; ++w) s += spart[tid * 8 + w];
        g_scores[b * S_ + s0 + tid] = s;
    }
}

// ============================================================
// Kernel 3: masked softmax stats. grid B, block 256
// ============================================================
__global__ void stats_kernel(const void* __restrict__ lens) {
    __shared__ float red[256];
    int b = blockIdx.x, tid = threadIdx.x;
    int len = load_len(lens, b);

    float m = -3.4e38f;
    for (int s = tid; s < S_; s += 256)
        if (s < len) m = fmaxf(m, g_scores[b * S_ + s]);
    red[tid] = m;
    __syncthreads();
    for (int o = 128; o > 0; o >>= 1) {
        if (tid < o) red[tid] = fmaxf(red[tid], red[tid + o]);
        __syncthreads();
    }
    m = red[0];
    __syncthreads();

    float sum = 0.f;
    for (int s = tid; s < S_; s += 256)
        if (s < len) sum += __expf(g_scores[b * S_ + s] - m);
    red[tid] = sum;
    __syncthreads();
    for (int o = 128; o > 0; o >>= 1) {
        if (tid < o) red[tid] += red[tid + o];
        __syncthreads();
    }
    if (tid == 0) { g_stats[2 * b] = m; g_stats[2 * b + 1] = red[0]; }
}

// ============================================================
// Kernel 4a: context partials. grid (16, B), block 128
// ============================================================
__global__ void context_part_kernel(const float* __restrict__ mb,
                                    const void* __restrict__ lens,
                                    float* __restrict__ out) {
    __shared__ float w[512];
    int b = blockIdx.y, tid = threadIdx.x;
    int dch = blockIdx.x & 3, sch = blockIdx.x >> 2;
    int len = load_len(lens, b);
    float m = g_stats[2 * b];
    float inv = __fdividef(1.f, g_stats[2 * b + 1]);

    int sbase = sch * 512;
    for (int i = tid; i < 512; i += 128) {
        int s = sbase + i;
        w[i] = (s < len) ? __expf(g_scores[b * S_ + s] - m) * inv : 0.f;
    }
    __syncthreads();

    if (dch == 0) {
        float* align_out = out + B_ * D_;
        for (int i = tid; i < 512; i += 128) align_out[b * S_ + sbase + i] = w[i];
    }

    int d = dch * 128 + tid;
    const float* p = mb + (size_t)b * S_ * D_ + (size_t)sbase * D_ + d;
    float acc = 0.f;
#pragma unroll 8
    for (int i = 0; i < 512; ++i) acc += w[i] * p[(size_t)i * D_];
    g_ctx[sch][b * D_ + d] = acc;
}

// ============================================================
// Kernel 4b: combine partials. grid B, block 128
// ============================================================
__global__ void combine_kernel(float* __restrict__ out) {
    int b = blockIdx.x, tid = threadIdx.x;
    for (int d = tid; d < D_; d += 128) {
        int i = b * D_ + d;
        out[i] = g_ctx[0][i] + g_ctx[1][i] + g_ctx[2][i] + g_ctx[3][i];
    }
}

// ============================================================
extern "C" void kernel_launch(void* const* d_in, const int* in_sizes, int n_in,
                              void* d_out, int out_size) {
    const float* source = (const float*)d_in[0];
    const float* mb     = (const float*)d_in[1];
    const void*  lens   = (const void*)d_in[2];
    const float* Wq     = (const float*)d_in[3];
    const float* bq     = (const float*)d_in[4];
    const float* Wc     = (const float*)d_in[5];
    const float* v      = (const float*)d_in[6];
    float*       out    = (float*)d_out;

    cudaFuncSetAttribute(scores_kernel,
                         cudaFuncAttributeMaxDynamicSharedMemorySize, SMEM_BYTES);

    prep_wc_kernel<<<D_, 512>>>(Wc);
    wq_kernel<<<dim3(4, B_), 128>>>(source, Wq, bq);
    scores_kernel<<<dim3(S_ / TM, B_), 512, SMEM_BYTES>>>(mb, v);
    stats_kernel<<<B_, 256>>>(lens);
    context_part_kernel<<<dim3(16, B_), 128>>>(mb, lens, out);
    combine_kernel<<<B_, 128>>>(out);
}

// round 5
// speedup vs baseline: 3.6267x; 1.0382x over previous
#include <cuda_runtime.h>
#include <cuda_bf16.h>
#include <cstdint>

#define B_ 64
#define S_ 2048
#define D_ 512

#define TM 64            // M rows per CTA
#define TK 32            // K per stage tile
#define NKT (D_ / TK)    // 16 k-tiles
#define NSCH 8           // context S-chunks

// ---------------- scratch globals ----------------
__device__ float g_wq[B_ * D_];
__device__ float g_scores[B_ * S_];
__device__ float g_stats[2 * B_];
__device__ float g_ctx[NSCH][B_ * D_];
// Wc in mma-fragment order: [kb][kk][wc][j2][lane][4]  (tf32 RNA-rounded)
#define BSZ (TK * D_)    // floats per k-tile = 16384
__device__ __align__(16) float g_wcF[NKT][BSZ];

// ---------------- helpers ----------------
__device__ __forceinline__ float to_tf32(float x) {
    asm("cvt.rna.tf32.f32 %0, %0;" : "+f"(x));
    return x;
}
__device__ __forceinline__ float fast_tanh(float x) {
    float xc = fminf(fmaxf(x, -15.f), 15.f);
    float e = __expf(2.f * xc);
    return __fdividef(e - 1.f, e + 1.f);
}
// memory_lengths dtype sniff (int64 vs int32): word[1]==0 iff int64 (LE)
__device__ __forceinline__ int load_len(const void* lens, int b) {
    const int* p32 = (const int*)lens;
    if (p32[1] == 0) return (int)((const long long*)lens)[b];
    return p32[b];
}
__device__ __forceinline__ uint32_t smem_u32(const void* p) {
    uint32_t a;
    asm("{ .reg .u64 t; cvta.to.shared.u64 t, %1; cvt.u32.u64 %0, t; }" : "=r"(a) : "l"(p));
    return a;
}
__device__ __forceinline__ void cp_async16(uint32_t dst, const void* src) {
    asm volatile("cp.async.cg.shared.global [%0], [%1], 16;" :: "r"(dst), "l"(src));
}
__device__ __forceinline__ void mma_tf32(float* c, const uint32_t* a,
                                         uint32_t b0, uint32_t b1) {
    asm volatile(
        "mma.sync.aligned.m16n8k8.row.col.f32.tf32.tf32.f32 "
        "{%0,%1,%2,%3}, {%4,%5,%6,%7}, {%8,%9}, {%0,%1,%2,%3};"
        : "+f"(c[0]), "+f"(c[1]), "+f"(c[2]), "+f"(c[3])
        : "r"(a[0]), "r"(a[1]), "r"(a[2]), "r"(a[3]), "r"(b0), "r"(b1));
}

// ============================================================
// Kernel 0: prep Wc -> g_wcF (fragment order, tf32).
// One thread per 4-float pack. grid 128, block 512.
// pack p: lane=g*4+t | j2 | wc | kk | kb ; floats = {je_b0, je_b1, jo_b0, jo_b1}
// ============================================================
__global__ void prep_wc_kernel(const float* __restrict__ Wc) {
    int p = blockIdx.x * 512 + threadIdx.x;     // 65536 packs
    int lane = p & 31;
    int j2   = (p >> 5) & 3;
    int wc   = (p >> 7) & 7;
    int kk   = (p >> 10) & 3;
    int kb   = (p >> 12) & 15;
    int g = lane >> 2, t = lane & 3;
    int e0 = wc * 64 + (j2 * 2) * 8 + g;        // j even
    int e1 = e0 + 8;                            // j odd
    int k0 = kb * 32 + kk * 8 + t;
    int k1 = k0 + 4;
    float4 f;
    f.x = to_tf32(Wc[(size_t)e0 * D_ + k0]);
    f.y = to_tf32(Wc[(size_t)e0 * D_ + k1]);
    f.z = to_tf32(Wc[(size_t)e1 * D_ + k0]);
    f.w = to_tf32(Wc[(size_t)e1 * D_ + k1]);
    ((float4*)g_wcF)[p] = f;
}

// ============================================================
// Kernel 1: wq = source @ Wq^T + bq.  grid (4, B), block 128
// ============================================================
__global__ void wq_kernel(const float* __restrict__ src,
                          const float* __restrict__ Wq,
                          const float* __restrict__ bq) {
    int b = blockIdx.y;
    int e = blockIdx.x * 128 + threadIdx.x;
    __shared__ __align__(16) float s_src[D_];
    for (int i = threadIdx.x; i < D_; i += 128) s_src[i] = src[b * D_ + i];
    __syncthreads();
    const float4* w4 = (const float4*)(Wq + (size_t)e * D_);
    const float4* s4 = (const float4*)s_src;
    float acc = 0.f;
#pragma unroll 8
    for (int i = 0; i < D_ / 4; ++i) {
        float4 wv = w4[i], xv = s4[i];
        acc += wv.x * xv.x + wv.y * xv.y + wv.z * xv.z + wv.w * xv.w;
    }
    g_wq[b * D_ + e] = acc + bq[e];
}

// ============================================================
// Kernel 2: fused scores, tf32 mma.sync, fragment-packed operands,
// cp.async double-buffered. grid (S/64, B), block 512 (2wr x 8wc).
// ============================================================
#define ASZ (TM * TK)               // 2048 floats per A buffer (fragment order)
#define OF_AS   0
#define OF_BS   (2 * ASZ)
#define OF_WQ   (OF_BS + 2 * BSZ)
#define OF_V    (OF_WQ + D_)
#define OF_PART (OF_V + D_)
#define SMEM_FLOATS (OF_PART + TM * 8)
#define SMEM_BYTES  (SMEM_FLOATS * 4)

// A fragment float index for element (row r in 0..63, k in 0..31)
__device__ __forceinline__ int a_frag_idx(int r, int k) {
    int kk = k >> 3, t = k & 3, k4 = (k >> 2) & 1;
    int wr = r >> 5, mt = (r >> 4) & 1, pm = (r >> 3) & 1, g = r & 7;
    return (((kk * 2 + wr) * 2 + mt) * 32 + (g * 4 + t)) * 4 + (k4 * 2 + pm);
}

__global__ void __launch_bounds__(512, 1)
scores_kernel(const float* __restrict__ mb, const float* __restrict__ vvec) {
    extern __shared__ __align__(16) float sm[];
    float* As    = sm + OF_AS;
    float* Bs    = sm + OF_BS;
    float* swq   = sm + OF_WQ;
    float* sv    = sm + OF_V;
    float* spart = sm + OF_PART;

    const int b   = blockIdx.y;
    const int s0  = blockIdx.x * TM;
    const int tid = threadIdx.x;
    const int wid = tid >> 5, lane = tid & 31;
    const int g = lane >> 2, t = lane & 3;
    const int wr = wid >> 3, wc = wid & 7;
    const int m0 = wr * 32, n0 = wc * 64;

    for (int i = tid; i < D_; i += 512) {
        swq[i] = g_wq[b * D_ + i];
        sv[i]  = vvec[i];
    }

    // staging indices: thread -> (row, 4 consecutive k)
    const int am   = tid >> 3;
    const int koff = (tid & 7) * 4;
    const float* a_gbase = mb + (size_t)b * S_ * D_ + (size_t)(s0 + am) * D_ + koff;
    const uint32_t sbase = smem_u32(sm);
    int afi[4];
#pragma unroll
    for (int i = 0; i < 4; ++i) afi[i] = a_frag_idx(am, koff + i);

    float acc[2][8][4];
#pragma unroll
    for (int mt = 0; mt < 2; ++mt)
#pragma unroll
        for (int j = 0; j < 8; ++j)
#pragma unroll
            for (int q = 0; q < 4; ++q) acc[mt][j][q] = 0.f;

    // ---- prologue: stage tile 0 ----
    {
        const float* bsrc = g_wcF[0];
        uint32_t bdst = sbase + OF_BS * 4;
#pragma unroll
        for (int c = 0; c < 8; ++c)
            cp_async16(bdst + (tid + c * 512) * 16, bsrc + (tid + c * 512) * 4);
        asm volatile("cp.async.commit_group;" ::: "memory");
        float4 av = *(const float4*)a_gbase;
        As[afi[0]] = to_tf32(av.x);
        As[afi[1]] = to_tf32(av.y);
        As[afi[2]] = to_tf32(av.z);
        As[afi[3]] = to_tf32(av.w);
    }

#pragma unroll 1
    for (int kb = 0; kb < NKT; ++kb) {
        const int cur = kb & 1;
        float4 av;
        if (kb < NKT - 1) {
            av = *(const float4*)(a_gbase + (kb + 1) * TK);
            const float* bsrc = g_wcF[kb + 1];
            uint32_t bdst = sbase + (OF_BS + (cur ^ 1) * BSZ) * 4;
#pragma unroll
            for (int c = 0; c < 8; ++c)
                cp_async16(bdst + (tid + c * 512) * 16, bsrc + (tid + c * 512) * 4);
            asm volatile("cp.async.commit_group;" ::: "memory");
            asm volatile("cp.async.wait_group 1;" ::: "memory");
        } else {
            asm volatile("cp.async.wait_group 0;" ::: "memory");
        }
        __syncthreads();

        const float* Ac = As + cur * ASZ;
        const float* Bc = Bs + cur * BSZ;
#pragma unroll
        for (int kk = 0; kk < 4; ++kk) {
            uint32_t a[2][4];
#pragma unroll
            for (int mt = 0; mt < 2; ++mt) {
                float4 af = *(const float4*)(Ac + ((kk * 2 + wr) * 2 + mt) * 128 + lane * 4);
                a[mt][0] = __float_as_uint(af.x);
                a[mt][1] = __float_as_uint(af.y);
                a[mt][2] = __float_as_uint(af.z);
                a[mt][3] = __float_as_uint(af.w);
            }
            const float* brow = Bc + ((kk * 8 + wc) * 4) * 128 + lane * 4;
#pragma unroll
            for (int j2 = 0; j2 < 4; ++j2) {
                float4 bf = *(const float4*)(brow + j2 * 128);
                uint32_t b0 = __float_as_uint(bf.x), b1 = __float_as_uint(bf.y);
                uint32_t b2 = __float_as_uint(bf.z), b3 = __float_as_uint(bf.w);
                mma_tf32(acc[0][j2 * 2],     a[0], b0, b1);
                mma_tf32(acc[1][j2 * 2],     a[1], b0, b1);
                mma_tf32(acc[0][j2 * 2 + 1], a[0], b2, b3);
                mma_tf32(acc[1][j2 * 2 + 1], a[1], b2, b3);
            }
        }

        if (kb < NKT - 1) {
            float* Ad = As + (cur ^ 1) * ASZ;
            Ad[afi[0]] = to_tf32(av.x);
            Ad[afi[1]] = to_tf32(av.y);
            Ad[afi[2]] = to_tf32(av.z);
            Ad[afi[3]] = to_tf32(av.w);
        }
        __syncthreads();
    }

    // ---- epilogue: tanh + v dot, reduce ----
    float p[4] = {0.f, 0.f, 0.f, 0.f};
#pragma unroll
    for (int mt = 0; mt < 2; ++mt)
#pragma unroll
        for (int j = 0; j < 8; ++j) {
            const int c = n0 + j * 8 + 2 * t;
            const float v0 = sv[c], v1 = sv[c + 1];
            const float w0 = swq[c], w1 = swq[c + 1];
            p[mt * 2 + 0] += fast_tanh(w0 + acc[mt][j][0]) * v0 +
                             fast_tanh(w1 + acc[mt][j][1]) * v1;
            p[mt * 2 + 1] += fast_tanh(w0 + acc[mt][j][2]) * v0 +
                             fast_tanh(w1 + acc[mt][j][3]) * v1;
        }
#pragma unroll
    for (int q = 0; q < 4; ++q) {
        p[q] += __shfl_xor_sync(0xFFFFFFFFu, p[q], 1);
        p[q] += __shfl_xor_sync(0xFFFFFFFFu, p[q], 2);
    }
    if (t == 0) {
#pragma unroll
        for (int mt = 0; mt < 2; ++mt) {
            spart[(m0 + mt * 16 + g) * 8 + wc]     = p[mt * 2 + 0];
            spart[(m0 + mt * 16 + g + 8) * 8 + wc] = p[mt * 2 + 1];
        }
    }
    __syncthreads();
    if (tid < TM) {
        float s = 0.f;
#pragma unroll
        for (int w = 0; w < 8; ++w) s += spart[tid * 8 + w];
        g_scores[b * S_ + s0 + tid] = s;
    }
}

// ============================================================
// Kernel 3: masked softmax stats. grid B, block 1024
// ============================================================
__global__ void stats_kernel(const void* __restrict__ lens) {
    __shared__ float red[1024];
    int b = blockIdx.x, tid = threadIdx.x;
    int len = load_len(lens, b);

    float m = -3.4e38f;
    for (int s = tid; s < S_; s += 1024)
        if (s < len) m = fmaxf(m, g_scores[b * S_ + s]);
    red[tid] = m;
    __syncthreads();
    for (int o = 512; o > 0; o >>= 1) {
        if (tid < o) red[tid] = fmaxf(red[tid], red[tid + o]);
        __syncthreads();
    }
    m = red[0];
    __syncthreads();

    float sum = 0.f;
    for (int s = tid; s < S_; s += 1024)
        if (s < len) sum += __expf(g_scores[b * S_ + s] - m);
    red[tid] = sum;
    __syncthreads();
    for (int o = 512; o > 0; o >>= 1) {
        if (tid < o) red[tid] += red[tid + o];
        __syncthreads();
    }
    if (tid == 0) { g_stats[2 * b] = m; g_stats[2 * b + 1] = red[0]; }
}

// ============================================================
// Kernel 4a: context partials. grid (32, B): x = dch(4) + 4*sch(8). block 128
// ============================================================
__global__ void context_part_kernel(const float* __restrict__ mb,
                                    const void* __restrict__ lens,
                                    float* __restrict__ out) {
    __shared__ float w[256];
    int b = blockIdx.y, tid = threadIdx.x;
    int dch = blockIdx.x & 3, sch = blockIdx.x >> 2;
    int len = load_len(lens, b);
    float m = g_stats[2 * b];
    float inv = __fdividef(1.f, g_stats[2 * b + 1]);

    int sbase = sch * 256;
    for (int i = tid; i < 256; i += 128) {
        int s = sbase + i;
        w[i] = (s < len) ? __expf(g_scores[b * S_ + s] - m) * inv : 0.f;
    }
    __syncthreads();

    if (dch == 0) {
        float* align_out = out + B_ * D_;
        for (int i = tid; i < 256; i += 128) align_out[b * S_ + sbase + i] = w[i];
    }

    int d = dch * 128 + tid;
    const float* p = mb + (size_t)b * S_ * D_ + (size_t)sbase * D_ + d;
    float acc = 0.f;
#pragma unroll 8
    for (int i = 0; i < 256; ++i) acc += w[i] * p[(size_t)i * D_];
    g_ctx[sch][b * D_ + d] = acc;
}

// ============================================================
// Kernel 4b: combine partials. grid B, block 128
// ============================================================
__global__ void combine_kernel(float* __restrict__ out) {
    int b = blockIdx.x, tid = threadIdx.x;
    for (int d = tid; d < D_; d += 128) {
        int i = b * D_ + d;
        float s = 0.f;
#pragma unroll
        for (int c = 0; c < NSCH; ++c) s += g_ctx[c][i];
        out[i] = s;
    }
}

// ============================================================
extern "C" void kernel_launch(void* const* d_in, const int* in_sizes, int n_in,
                              void* d_out, int out_size) {
    const float* source = (const float*)d_in[0];
    const float* mb     = (const float*)d_in[1];
    const void*  lens   = (const void*)d_in[2];
    const float* Wq     = (const float*)d_in[3];
    const float* bq     = (const float*)d_in[4];
    const float* Wc     = (const float*)d_in[5];
    const float* v      = (const float*)d_in[6];
    float*       out    = (float*)d_out;

    cudaFuncSetAttribute(scores_kernel,
                         cudaFuncAttributeMaxDynamicSharedMemorySize, SMEM_BYTES);

    prep_wc_kernel<<<128, 512>>>(Wc);
    wq_kernel<<<dim3(4, B_), 128>>>(source, Wq, bq);
    scores_kernel<<<dim3(S_ / TM, B_), 512, SMEM_BYTES>>>(mb, v);
    stats_kernel<<<B_, 1024>>>(lens);
    context_part_kernel<<<dim3(32, B_), 128>>>(mb, lens, out);
    combine_kernel<<<B_, 128>>>(out);
}